// round 11
// baseline (speedup 1.0000x reference)
#include <cuda_runtime.h>
#include <cstdint>

#define SEQ 2048
#define DK  128

// ---------------- static device scratch (no allocations allowed) ------------
__device__ float g_Pqk[(size_t)SEQ * SEQ];   // P_qk[i][l] = q_i . k_l
__device__ float g_Pvv[(size_t)SEQ * SEQ];   // P_vv[i][l] = v_i . v_l
__device__ float g_U[(size_t)SEQ * DK];      // u_l = Sqq_l k_l (incl 1/(l+1))
// per-step chain constants, 8 floats per step:
// [0..3]={s_l, kqq_l, vv_l, 1/(l+1)}  [4..7]={k1q, k1u, vvm, l/(l+1)}
__device__ float g_chain[(size_t)SEQ * 8];

// ---------------- f32x2 packed helpers (sm_103a) ----------------------------
__device__ __forceinline__ unsigned long long ffma2(unsigned long long a,
                                                    unsigned long long b,
                                                    unsigned long long c) {
    unsigned long long d;
    asm("fma.rn.f32x2 %0, %1, %2, %3;" : "=l"(d) : "l"(a), "l"(b), "l"(c));
    return d;
}
__device__ __forceinline__ unsigned long long fmul2(unsigned long long a,
                                                    unsigned long long b) {
    unsigned long long d;
    asm("mul.rn.f32x2 %0, %1, %2;" : "=l"(d) : "l"(a), "l"(b));
    return d;
}
__device__ __forceinline__ unsigned long long fadd2(unsigned long long a,
                                                    unsigned long long b) {
    unsigned long long d;
    asm("add.rn.f32x2 %0, %1, %2;" : "=l"(d) : "l"(a), "l"(b));
    return d;
}
__device__ __forceinline__ unsigned long long pk2(float lo, float hi) {
    unsigned long long r;
    asm("mov.b64 %0, {%1, %2};" : "=l"(r) : "f"(lo), "f"(hi));
    return r;
}
__device__ __forceinline__ float2 upk2(unsigned long long a) {
    float2 f;
    asm("mov.b64 {%0, %1}, %2;" : "=f"(f.x), "=f"(f.y) : "l"(a));
    return f;
}

// ---------------- Phase 1a: both Gram matrices in one launch ----------------
__global__ void __launch_bounds__(256) k_gemm(const float* __restrict__ q,
                                              const float* __restrict__ kk_,
                                              const float* __restrict__ v) {
    if (blockIdx.y > blockIdx.x) return;
    const float* A; const float* B; float* C;
    if (blockIdx.z == 0) { A = q; B = kk_; C = g_Pqk; }
    else                 { A = v; B = v;   C = g_Pvv; }
    __shared__ float As[32][68];
    __shared__ float Bs[32][68];
    const int tx = threadIdx.x & 15, ty = threadIdx.x >> 4;
    const int i0 = blockIdx.y * 64, l0 = blockIdx.x * 64;
    const int t = threadIdx.x;
    const int r = t >> 2, cc = (t & 3) * 8;
    float acc[4][4] = {};
    for (int k0 = 0; k0 < DK; k0 += 32) {
        float4 a0 = *(const float4*)&A[(size_t)(i0 + r) * DK + k0 + cc];
        float4 a1 = *(const float4*)&A[(size_t)(i0 + r) * DK + k0 + cc + 4];
        float4 b0 = *(const float4*)&B[(size_t)(l0 + r) * DK + k0 + cc];
        float4 b1 = *(const float4*)&B[(size_t)(l0 + r) * DK + k0 + cc + 4];
        __syncthreads();
        As[cc + 0][r] = a0.x; As[cc + 1][r] = a0.y; As[cc + 2][r] = a0.z; As[cc + 3][r] = a0.w;
        As[cc + 4][r] = a1.x; As[cc + 5][r] = a1.y; As[cc + 6][r] = a1.z; As[cc + 7][r] = a1.w;
        Bs[cc + 0][r] = b0.x; Bs[cc + 1][r] = b0.y; Bs[cc + 2][r] = b0.z; Bs[cc + 3][r] = b0.w;
        Bs[cc + 4][r] = b1.x; Bs[cc + 5][r] = b1.y; Bs[cc + 6][r] = b1.z; Bs[cc + 7][r] = b1.w;
        __syncthreads();
#pragma unroll
        for (int kv = 0; kv < 32; kv++) {
            float4 av = *(const float4*)&As[kv][ty * 4];
            float4 bv = *(const float4*)&Bs[kv][tx * 4];
            float a[4] = {av.x, av.y, av.z, av.w};
            float b[4] = {bv.x, bv.y, bv.z, bv.w};
#pragma unroll
            for (int i = 0; i < 4; i++)
#pragma unroll
                for (int j = 0; j < 4; j++) acc[i][j] += a[i] * b[j];
        }
    }
#pragma unroll
    for (int i = 0; i < 4; i++) {
        float4 o = make_float4(acc[i][0], acc[i][1], acc[i][2], acc[i][3]);
        *(float4*)&C[(size_t)(i0 + ty * 4 + i) * SEQ + l0 + tx * 4] = o;
    }
}

// ---------------- Phase 1b: U + k1u dot -------------------------------------
__global__ void __launch_bounds__(256) k_U(const float* __restrict__ Q,
                                           const float* __restrict__ KK) {
    __shared__ float sh[128][8];
    __shared__ float red[8][4];
    const int tid = threadIdx.x;
    const int d = tid & 127, jh = tid >> 7;
    const int l0 = blockIdx.x * 8;
    float acc[4] = {0.f, 0.f, 0.f, 0.f};
    for (int i0 = 0; i0 <= l0 + 7; i0 += 128) {
        const int r = tid >> 1, c4 = (tid & 1) * 4;
        const int irow = i0 + r;
        float4 pv = *(const float4*)&g_Pqk[(size_t)irow * SEQ + l0 + c4];
        if (irow > l0 + c4 + 0) pv.x = 0.f;
        if (irow > l0 + c4 + 1) pv.y = 0.f;
        if (irow > l0 + c4 + 2) pv.z = 0.f;
        if (irow > l0 + c4 + 3) pv.w = 0.f;
        __syncthreads();
        *(float4*)&sh[r][c4] = pv;
        __syncthreads();
#pragma unroll 8
        for (int r2 = 0; r2 < 128; r2++) {
            float qv = Q[(size_t)(i0 + r2) * DK + d];
            float4 s4 = *(const float4*)&sh[r2][jh * 4];
            acc[0] += qv * s4.x; acc[1] += qv * s4.y;
            acc[2] += qv * s4.z; acc[3] += qv * s4.w;
        }
    }
    float uval[4];
#pragma unroll
    for (int jl = 0; jl < 4; jl++) {
        const int l = l0 + jh * 4 + jl;
        uval[jl] = acc[jl] / (float)(l + 1);
        g_U[(size_t)l * DK + d] = uval[jl];
    }
#pragma unroll
    for (int jl = 0; jl < 4; jl++) {
        const int l = l0 + jh * 4 + jl;
        float p = (l >= 1) ? uval[jl] * KK[(size_t)(l - 1) * DK + d] : 0.f;
#pragma unroll
        for (int o = 16; o > 0; o >>= 1)
            p += __shfl_down_sync(0xffffffffu, p, o);
        if ((tid & 31) == 0) red[tid >> 5][jl] = p;
    }
    __syncthreads();
    if (tid < 8) {
        const int jh2 = tid >> 2, jl2 = tid & 3;
        const int l = l0 + jh2 * 4 + jl2;
        const int w0 = jh2 * 4;
        g_chain[(size_t)l * 8 + 5] =
            red[w0][jl2] + red[w0 + 1][jl2] + red[w0 + 2][jl2] + red[w0 + 3][jl2];
    }
}

// ---------------- Phase 1c: per-step scalars + near dots --------------------
__global__ void __launch_bounds__(256) k_scal(const float* __restrict__ q,
                                              const float* __restrict__ kk_,
                                              const float* __restrict__ v) {
    const int tid = threadIdx.x;
    const int c = tid & 63;
    const int rq = tid >> 6;
    const int l0 = blockIdx.x * 64;
    const int l = l0 + c;
    float ss = 0.f, k2 = 0.f;
    const int ntiles = blockIdx.x + 1;
    for (int tt = 0; tt < ntiles; tt++) {
        const int ib = tt * 64 + rq * 16;
#pragma unroll 4
        for (int j = 0; j < 16; j++) {
            const int i = ib + j;
            if (i <= l) {
                float pq = g_Pqk[(size_t)i * SEQ + l];
                float pv = g_Pvv[(size_t)i * SEQ + l];
                ss += pq * pv;
                k2 += pq * pq;
            }
        }
    }
    __shared__ float rs[4][64], rk[4][64];
    rs[rq][c] = ss; rk[rq][c] = k2;
    __syncthreads();
    if (tid < 64) {
        float s  = rs[0][tid] + rs[1][tid] + rs[2][tid] + rs[3][tid];
        float kq = rk[0][tid] + rk[1][tid] + rk[2][tid] + rk[3][tid];
        const int ll = l0 + tid;
        const float fl = (float)(ll + 1);
        const float bm = 1.0f / fl;
        *(float4*)&g_chain[(size_t)ll * 8] =
            make_float4(s * bm, kq * bm, g_Pvv[(size_t)ll * SEQ + ll], bm);
    }
    // near dots: k1q = k_{l-1}.q_l ; vvm = v_{l-1}.v_l  (4 threads per column)
    const int lc = tid >> 2, td = tid & 3;
    const int ln = l0 + lc;
    float akq = 0.f, avv = 0.f;
    if (ln >= 1) {
        const float4* qp = (const float4*)&q[(size_t)ln * DK + td * 32];
        const float4* kp = (const float4*)&kk_[(size_t)(ln - 1) * DK + td * 32];
        const float4* vp = (const float4*)&v[(size_t)ln * DK + td * 32];
        const float4* wp = (const float4*)&v[(size_t)(ln - 1) * DK + td * 32];
#pragma unroll
        for (int x = 0; x < 8; x++) {
            float4 a = kp[x], b = qp[x], cv = wp[x], dv = vp[x];
            akq += a.x * b.x + a.y * b.y + a.z * b.z + a.w * b.w;
            avv += cv.x * dv.x + cv.y * dv.y + cv.z * dv.z + cv.w * dv.w;
        }
    }
    akq += __shfl_down_sync(0xffffffffu, akq, 2);
    akq += __shfl_down_sync(0xffffffffu, akq, 1);
    avv += __shfl_down_sync(0xffffffffu, avv, 2);
    avv += __shfl_down_sync(0xffffffffu, avv, 1);
    if (td == 0) {
        g_chain[(size_t)ln * 8 + 4] = akq;
        g_chain[(size_t)ln * 8 + 6] = avv;
        g_chain[(size_t)ln * 8 + 7] = (float)ln / (float)(ln + 1);
    }
}

// ---------------- Phase 2: pipelined sequential recursion -------------------
// 544 threads: warps 0-15 compute (warps 1-4 also reduce), warp 16 = chain.
// Lag-2 pipeline identical to R6, but the serial scalar chain no longer sits
// on a compute warp's critical path.
__global__ void __launch_bounds__(544) k_seq(const float* __restrict__ q,
                                             const float* __restrict__ kg,
                                             const float* __restrict__ v,
                                             float* __restrict__ out) {
    // unified vector buffer: q ring2 [0,256) | k ring4 [256,768)
    //                      | v ring4 [768,1280) | u ring2 [1280,1536)
    __shared__ float  vbuf[1536];
    __shared__ float2 part[512];
    __shared__ float4 wsumb[2][4];
    __shared__ float4 coeff[2];
    __shared__ float  sigf;

    const int tid = threadIdx.x;
    const bool is_compute = tid < 512;
    const int seg = (tid >> 7) & 3;
    const int row = tid & 127;

    const int stg_base = (seg == 0) ? 0 : (seg == 1) ? 256 : (seg == 2) ? 768 : 1280;
    const int rmask = (seg == 1 || seg == 2) ? 3 : 1;
    const float* src = (seg == 0) ? q : (seg == 1) ? kg : (seg == 2) ? v : g_U;

    unsigned long long Jp[16];
#pragma unroll
    for (int c = 0; c < 16; c++) Jp[c] = 0ull;

    // chain-role state (warp 16)
    float S = 0.f, T = 0.f, trS = 0.f;
    float sig_m = 1.f, sig_p = 1.f;
    float cp = 0.f, dp = 0.f, vvprev = 0.f;
    float4 pA = {0, 0, 0, 0}, pB = {0, 0, 0, 0};
    float4 nA = {0, 0, 0, 0}, nB = {0, 0, 0, 0};

    // zero rings, init coeffs
    if (is_compute) { vbuf[tid] = 0.f; vbuf[tid + 512] = 0.f; vbuf[tid + 1024] = 0.f; }
    if (tid == 0) {
        coeff[0] = make_float4(1.f, 0.f, 0.f, 0.f);
        coeff[1] = make_float4(1.f, 0.f, 0.f, 0.f);
        sigf = 1.f;
    }
    __syncthreads();
    float nx1 = 0.f, nx2 = 0.f;
    if (is_compute) {
        vbuf[stg_base + row] = src[row];
        nx1 = src[(size_t)1 * DK + row];
        nx2 = src[(size_t)2 * DK + row];
    } else {
        const float4* ch = (const float4*)g_chain;
        pA = ch[0]; pB = ch[1];
        nA = ch[2]; nB = ch[3];
    }
    __syncthreads();

#pragma unroll 2
    for (int i = 0; i <= SEQ; i++) {
        const int par = i & 1;

        if (is_compute) {
            // ---- (a) apply published update for step i-2 --------------------
            {
                float4 cc = coeff[par];
                if (cc.x != 1.f || cc.y != 0.f) {
                    const int s2 = (i - 2) & 3;
                    const float bv = cc.y * vbuf[768 + s2 * 128 + row];
                    const unsigned long long bvp = pk2(bv, bv);
                    const ulonglong2* kp = (const ulonglong2*)&vbuf[256 + s2 * 128 + seg * 32];
                    if (cc.x == 1.f) {
#pragma unroll
                        for (int c = 0; c < 8; c++) {
                            ulonglong2 kv = kp[c];
                            Jp[2 * c + 0] = ffma2(kv.x, bvp, Jp[2 * c + 0]);
                            Jp[2 * c + 1] = ffma2(kv.y, bvp, Jp[2 * c + 1]);
                        }
                    } else {
                        const unsigned long long mp = pk2(cc.x, cc.x);
#pragma unroll
                        for (int c = 0; c < 8; c++) {
                            ulonglong2 kv = kp[c];
                            Jp[2 * c + 0] = ffma2(kv.x, bvp, fmul2(Jp[2 * c + 0], mp));
                            Jp[2 * c + 1] = ffma2(kv.y, bvp, fmul2(Jp[2 * c + 1], mp));
                        }
                    }
                }
            }

            // ---- (b) matvec row i vs Jhat ----------------------------------
            if (i < SEQ) {
                unsigned long long a1a = 0ull, a1b = 0ull, a2a = 0ull, a2b = 0ull;
                const ulonglong2* qp = (const ulonglong2*)&vbuf[par * 128 + seg * 32];
                const ulonglong2* up = (const ulonglong2*)&vbuf[1280 + par * 128 + seg * 32];
#pragma unroll
                for (int c2 = 0; c2 < 4; c2++) {
                    ulonglong2 q0 = qp[2 * c2], q1 = qp[2 * c2 + 1];
                    ulonglong2 u0 = up[2 * c2], u1 = up[2 * c2 + 1];
                    a1a = ffma2(Jp[4 * c2 + 0], q0.x, a1a);
                    a1b = ffma2(Jp[4 * c2 + 1], q0.y, a1b);
                    a1a = ffma2(Jp[4 * c2 + 2], q1.x, a1a);
                    a1b = ffma2(Jp[4 * c2 + 3], q1.y, a1b);
                    a2a = ffma2(Jp[4 * c2 + 0], u0.x, a2a);
                    a2b = ffma2(Jp[4 * c2 + 1], u0.y, a2b);
                    a2a = ffma2(Jp[4 * c2 + 2], u1.x, a2a);
                    a2b = ffma2(Jp[4 * c2 + 3], u1.y, a2b);
                }
                float2 f1a = upk2(a1a), f1b = upk2(a1b);
                float2 f2a = upk2(a2a), f2b = upk2(a2b);
                part[tid] = make_float2((f1a.x + f1a.y) + (f1b.x + f1b.y),
                                        (f2a.x + f2a.y) + (f2b.x + f2b.y));
            }

            // ---- (c) stage row i+1 (depth-2 prefetched), rotate ------------
            if (i + 1 < SEQ)
                vbuf[stg_base + ((i + 1) & rmask) * 128 + row] = nx1;
            nx1 = nx2;
            nx2 = (i + 3 < SEQ) ? src[(size_t)(i + 3) * DK + row] : 0.f;

            // ---- (d) split barrier + reduce role ---------------------------
            if (tid >= 32 && tid < 160) {
                asm volatile("bar.sync 1, 544;" ::: "memory");
                if (i < SEQ) {
                    const int j = tid - 32;
                    const unsigned long long* pp = (const unsigned long long*)part;
                    unsigned long long s01 = fadd2(pp[j], pp[j + 128]);
                    unsigned long long s23 = fadd2(pp[j + 256], pp[j + 384]);
                    float2 ab = upk2(fadd2(s01, s23));
                    float a = ab.x, b = ab.y;
                    float vl = vbuf[768 + (i & 3) * 128 + j];
                    float vm = vbuf[768 + ((i + 3) & 3) * 128 + j];
                    float x1 = vl * a, x2 = a * a, x3 = vl * b, x4 = vm * a;
#pragma unroll
                    for (int o = 16; o > 0; o >>= 1) {
                        x1 += __shfl_down_sync(0xffffffffu, x1, o);
                        x2 += __shfl_down_sync(0xffffffffu, x2, o);
                        x3 += __shfl_down_sync(0xffffffffu, x3, o);
                        x4 += __shfl_down_sync(0xffffffffu, x4, o);
                    }
                    if ((tid & 31) == 0)
                        wsumb[par][(tid >> 5) - 1] = make_float4(x1, x2, x3, x4);
                }
            } else {
                asm volatile("bar.arrive 1, 544;" ::: "memory");
            }
        } else {
            asm volatile("bar.arrive 1, 544;" ::: "memory");
            // ---- chain warp: scalar chain for step l = i-1 ------------------
            if (i > 0) {
                const int l = i - 1;
                float4 w0 = wsumb[1 - par][0], w1 = wsumb[1 - par][1];
                float4 w2 = wsumb[1 - par][2], w3 = wsumb[1 - par][3];
                const float B1 = w0.x + w1.x + w2.x + w3.x;
                const float B2 = w0.y + w1.y + w2.y + w3.y;
                const float B3 = w0.z + w1.z + w2.z + w3.z;
                const float B4 = w0.w + w1.w + w2.w + w3.w;

                const float s_l = pA.x, kqq = pA.y, vvl = pA.z, bmv = pA.w;
                const float kq = pB.x, ku = pB.y, vvm = pB.z, amv = pB.w;

                const float c2s = cp * sig_m;
                const float X1 = c2s * B1 + dp * kq * vvm;
                const float X3 = c2s * B3 + dp * ku * vvm;
                const float X2 = c2s * c2s * B2 + 2.f * c2s * dp * kq * B4
                               + dp * dp * kq * kq * vvprev;

                trS = amv * trS + vvl * bmv;
                const float sJ   = amv * S + bmv * X1;
                const float A_JJ = amv * T + bmv * X2;
                const float A_Jl = X3;
                const float A_ll = vvl * kqq;

                const bool first = (l == 0);
                const float A_JJ_s = (first || A_JJ == 0.f) ? 1.f : A_JJ;
                const float A_ll_s = (first || A_ll == 0.f) ? 1.f : A_ll;
                const float denom  = A_JJ * A_ll - A_Jl * A_Jl;
                const float denom_s = (first || denom == 0.f) ? 1.f : denom;

                const float margin = s_l - A_Jl * __fdividef(sJ, A_JJ_s);
                const float rden = __fdividef(1.f, denom_s);
                const float wf = (A_ll * sJ - A_Jl * s_l) * rden;
                const float wi = (A_JJ * s_l - A_Jl * sJ) * rden;
                const float wf_c = (wi <= 0.f) ? __fdividef(sJ, A_JJ_s)
                                               : ((wf <= 0.f) ? 0.f : wf);
                const float wi_c = (wi <= 0.f) ? 0.f
                                               : ((wf <= 0.f) ? __fdividef(s_l, A_ll_s) : wi);
                const bool do_upd = margin > 0.f;

                float cf, ci, upd;
                if (first)       { cf = 0.f;  ci = 1.f;  upd = 1.f; S = s_l; T = A_ll; }
                else if (do_upd) { cf = wf_c; ci = wi_c; upd = 1.f;
                                   S = cf * sJ + ci * s_l;
                                   T = cf * cf * A_JJ + 2.f * cf * ci * A_Jl + ci * ci * A_ll; }
                else             { cf = 1.f;  ci = 0.f;  upd = 0.f; S = sJ; T = A_JJ; }

                if (tid == 512) {
                    out[l] = 0.5f * trS - S + 0.5f * T;
                    out[SEQ + l] = upd;
                }

                float m, beta, signew;
                if (!(first || do_upd)) { m = 1.f; beta = 0.f; signew = sig_p; }
                else {
                    const float s2v = sig_p * cf;
                    if (cf == 0.f)  { m = 0.f; beta = ci; signew = 1.f; }
                    else if (fabsf(s2v) < 1e-12f || fabsf(s2v) > 1e12f)
                                    { m = s2v; beta = ci; signew = 1.f; }
                    else            { m = 1.f; beta = __fdividef(ci, s2v); signew = s2v; }
                }
                if (tid == 512) {
                    coeff[1 - par] = make_float4(m, beta, 0.f, 0.f);
                    if (i == SEQ) sigf = signew;
                }
                sig_m = sig_p; sig_p = signew;
                cp = cf; dp = ci; vvprev = vvl;
                pA = nA; pB = nB;
                if (l + 2 < SEQ) {
                    const float4* ch = (const float4*)&g_chain[(size_t)(l + 2) * 8];
                    nA = ch[0]; nB = ch[1];
                }
            }
        }
        __syncthreads();
    }

    // ---- epilogue: apply final update (step SEQ-1), write J = sigf*Jhat ----
    if (is_compute) {
        float4 cc = coeff[1];
        if (cc.x != 1.f || cc.y != 0.f) {
            const int s2 = (SEQ - 1) & 3;
            const float bv = cc.y * vbuf[768 + s2 * 128 + row];
            const unsigned long long bvp = pk2(bv, bv);
            const ulonglong2* kp = (const ulonglong2*)&vbuf[256 + s2 * 128 + seg * 32];
            if (cc.x == 1.f) {
#pragma unroll
                for (int c = 0; c < 8; c++) {
                    ulonglong2 kv = kp[c];
                    Jp[2 * c + 0] = ffma2(kv.x, bvp, Jp[2 * c + 0]);
                    Jp[2 * c + 1] = ffma2(kv.y, bvp, Jp[2 * c + 1]);
                }
            } else {
                const unsigned long long mp = pk2(cc.x, cc.x);
#pragma unroll
                for (int c = 0; c < 8; c++) {
                    ulonglong2 kv = kp[c];
                    Jp[2 * c + 0] = ffma2(kv.x, bvp, fmul2(Jp[2 * c + 0], mp));
                    Jp[2 * c + 1] = ffma2(kv.y, bvp, fmul2(Jp[2 * c + 1], mp));
                }
            }
        }
        const float sf = sigf;
#pragma unroll
        for (int c = 0; c < 16; c++) {
            float2 jf = upk2(Jp[c]);
            out[2 * SEQ + (size_t)row * DK + seg * 32 + 2 * c + 0] = sf * jf.x;
            out[2 * SEQ + (size_t)row * DK + seg * 32 + 2 * c + 1] = sf * jf.y;
        }
    }
}

// ---------------------------------------------------------------------------
extern "C" void kernel_launch(void* const* d_in, const int* in_sizes, int n_in,
                              void* d_out, int out_size) {
    const float* q = (const float*)d_in[0];
    const float* k = (const float*)d_in[1];
    const float* v = (const float*)d_in[2];
    float* out = (float*)d_out;

    dim3 gg(SEQ / 64, SEQ / 64, 2);
    k_gemm<<<gg, 256>>>(q, k, v);        // launch 0
    k_U<<<SEQ / 8, 256>>>(q, k);         // launch 1
    k_scal<<<SEQ / 64, 256>>>(q, k, v);  // launch 2
    k_seq<<<1, 544>>>(q, k, v, out);     // launch 3  <-- ncu capture slot
    (void)in_sizes; (void)n_in; (void)out_size;
}